// round 5
// baseline (speedup 1.0000x reference)
#include <cuda_runtime.h>
#include <math.h>

#define MAXB 32768

__device__ float g_pooled[MAXB * 64];    // [B][4 features * 16 dims]
__device__ float g_stats[128];           // [0:64) sum, [64:128) sumsq
__device__ float g_mu[64];
__device__ float g_var[64];

__device__ __forceinline__ float fm(float a, float b) { return __fmul_rn(a, b); }
__device__ __forceinline__ float fa(float a, float b) { return __fadd_rn(a, b); }

__global__ void zero_stats_kernel() {
    if (threadIdx.x < 128) g_stats[threadIdx.x] = 0.f;
}

// ---------------------------------------------------------------------------
// Pooling: ONE THREAD PER ROW, strictly sequential, literal transcription of
// the reference math (masked prefix, jax.nn.softmax with max-subtraction,
// first-max argmax, korder with clamped norm). No fmaf contraction.
// ---------------------------------------------------------------------------
__global__ __launch_bounds__(128) void pool3_kernel(
    const int* __restrict__ ug, const int* __restrict__ urbv,
    const int* __restrict__ mg, const int* __restrict__ mt,
    const int* __restrict__ ug_c, const int* __restrict__ urb_c,
    const int* __restrict__ mg_c, const int* __restrict__ mt_c,
    const float* __restrict__ emb_movie, const float* __restrict__ emb_tag,
    const float* __restrict__ emb_genre, const float* __restrict__ at_movie,
    int B)
{
    int row = blockIdx.x * 128 + threadIdx.x;
    if (row >= B) return;
    float* outp = g_pooled + row * 64;

    // ---- feature 0: 'sum', genre table ----
    {
        int cnt = ug_c[row];
        const int* idp = ug + row * 50;
        #pragma unroll
        for (int d = 0; d < 16; d++) {
            float p = 0.f;
            for (int pos = 0; pos < cnt; pos++)
                p = fa(p, emb_genre[idp[pos] * 16 + d]);
            outp[d] = p;
        }
    }
    // ---- feature 1: 'atten', movie table. Literal jax.nn.softmax over all
    //      50 positions of masked aw (masked entries are exactly 0). ----
    {
        int cnt = urb_c[row];
        const int* idp = urbv + row * 50;
        float av[50];
        for (int pos = 0; pos < cnt; pos++) av[pos] = at_movie[idp[pos]];
        // max over masked aw: valid entries and (50-cnt) zeros
        float M = (cnt < 50) ? 0.f : -1e30f;
        for (int pos = 0; pos < cnt; pos++) M = fmaxf(M, av[pos]);
        // denominator: sum of exp(aw - M) over all 50
        float den = fm((float)(50 - cnt), expf(-M));
        float w[50];
        for (int pos = 0; pos < cnt; pos++) {
            w[pos] = expf(__fadd_rn(av[pos], -M));
            den = fa(den, w[pos]);
        }
        float invden = __fdiv_rn(1.f, den);
        for (int pos = 0; pos < cnt; pos++) w[pos] = fm(w[pos], invden);
        #pragma unroll
        for (int d = 0; d < 16; d++) {
            float num = 0.f;
            for (int pos = 0; pos < cnt; pos++)
                num = fa(num, fm(emb_movie[idp[pos] * 16 + d], w[pos]));
            outp[16 + d] = num;
        }
    }
    // ---- feature 2: 'max' (first argmax of per-position L2), genre table ----
    {
        int cnt = mg_c[row];
        const int* idp = mg + row * 50;
        int bidx = -1;              // cnt==0 -> masked zeros win -> output 0
        float best = 0.f;           // masked positions have l2 == 0
        for (int pos = 0; pos < cnt; pos++) {
            const float* e = emb_genre + idp[pos] * 16;
            float l2 = 0.f;
            #pragma unroll
            for (int d = 0; d < 16; d++) l2 = fa(l2, fm(e[d], e[d]));
            if (l2 > best) { best = l2; bidx = pos; }
        }
        if (bidx >= 0) {
            const float* e = emb_genre + idp[bidx] * 16;
            #pragma unroll
            for (int d = 0; d < 16; d++) outp[32 + d] = e[d];
        } else {
            #pragma unroll
            for (int d = 0; d < 16; d++) outp[32 + d] = 0.f;
        }
    }
    // ---- feature 3: 'korder', tag table ----
    {
        int cnt = mt_c[row];
        const int* idp = mt + row * 50;
        float v[16];
        float n2 = 0.f;
        #pragma unroll
        for (int d = 0; d < 16; d++) {
            float s = 0.f, ss = 0.f;
            for (int pos = 0; pos < cnt; pos++) {
                float e = emb_tag[idp[pos] * 16 + d];
                s = fa(s, e);
                ss = fa(ss, fm(e, e));
            }
            float vv = fm(0.5f, __fadd_rn(fm(s, s), -ss));
            v[d] = vv;
            n2 = fa(n2, fm(vv, vv));
        }
        float n = fmaxf(__fsqrt_rn(n2), 1e-12f);
        float invn = __fdiv_rn(1.f, n);
        #pragma unroll
        for (int d = 0; d < 16; d++) outp[48 + d] = fm(v[d], invn);
    }
}

// ---------------------------------------------------------------------------
// BN statistics (structure proven order-insensitive in R1 vs R3).
// ---------------------------------------------------------------------------
__global__ void stats_kernel(int B) {
    int d = threadIdx.x;           // 0..63
    float s = 0.f, q = 0.f;
    for (int r = blockIdx.x; r < B; r += 256) {
        float v = g_pooled[r * 64 + d];
        s = fa(s, v);
        q = fa(q, fm(v, v));
    }
    atomicAdd(&g_stats[d], s);
    atomicAdd(&g_stats[64 + d], q);
}

__global__ void bn_kernel(int B) {
    int t = threadIdx.x;
    if (t >= 64) return;
    float invB = 1.f / (float)B;
    float mean = g_stats[t] * invB;
    float var  = g_stats[64 + t] * invB - mean * mean;
    g_mu[t] = mean;
    g_var[t] = var;
}

// ---------------------------------------------------------------------------
// MLP with literal BN application: (x - mu) * rsqrt(var + eps) * gamma + beta.
// ---------------------------------------------------------------------------
__global__ __launch_bounds__(128) void mlp_kernel(
    const int* __restrict__ uid, const int* __restrict__ mid,
    const int* __restrict__ yr,
    const float* __restrict__ emb_user, const float* __restrict__ emb_movie,
    const float* __restrict__ emb_year,
    const float* __restrict__ gamma, const float* __restrict__ beta,
    const float* __restrict__ W1, const float* __restrict__ b1,
    const float* __restrict__ W2, const float* __restrict__ b2,
    const float* __restrict__ W3, const float* __restrict__ b3,
    float* __restrict__ out, int B)
{
    __shared__ float4 sW1t[64 * 28];   // transposed: [j][i/4]
    __shared__ float4 sW2[64 * 8];
    __shared__ float  sb1[64], sMu[64], sR[64], sG[64], sBt[64];
    __shared__ float4 sb2[8], sW3[8];
    __shared__ float  sb3;
    int tid = threadIdx.x;
    for (int idx = tid; idx < 64 * 112; idx += 128) {
        int j = idx / 112, i = idx % 112;
        reinterpret_cast<float*>(sW1t)[j * 112 + i] = W1[i * 64 + j];
    }
    for (int idx = tid; idx < 64 * 8; idx += 128)
        sW2[idx] = reinterpret_cast<const float4*>(W2)[idx];
    if (tid < 64) {
        sb1[tid] = b1[tid];
        sMu[tid] = g_mu[tid];
        sR[tid]  = rsqrtf(__fadd_rn(g_var[tid], 1e-5f));
        sG[tid]  = gamma[tid];
        sBt[tid] = beta[tid];
    }
    if (tid < 8) {
        sb2[tid] = reinterpret_cast<const float4*>(b2)[tid];
        sW3[tid] = reinterpret_cast<const float4*>(W3)[tid];
    }
    if (tid == 0) sb3 = b3[0];
    __syncthreads();

    int row = blockIdx.x * 128 + tid;
    if (row >= B) return;

    float x[112];
    {
        const float4* p4 = reinterpret_cast<const float4*>(emb_user) + uid[row] * 4;
        #pragma unroll
        for (int q = 0; q < 4; q++) { float4 v = p4[q];
            x[q*4+0]=v.x; x[q*4+1]=v.y; x[q*4+2]=v.z; x[q*4+3]=v.w; }
    }
    {
        const float4* p4 = reinterpret_cast<const float4*>(emb_movie) + mid[row] * 4;
        #pragma unroll
        for (int q = 0; q < 4; q++) { float4 v = p4[q];
            x[16+q*4+0]=v.x; x[16+q*4+1]=v.y; x[16+q*4+2]=v.z; x[16+q*4+3]=v.w; }
    }
    {
        const float4* p4 = reinterpret_cast<const float4*>(emb_year) + yr[row] * 4;
        #pragma unroll
        for (int q = 0; q < 4; q++) { float4 v = p4[q];
            x[32+q*4+0]=v.x; x[32+q*4+1]=v.y; x[32+q*4+2]=v.z; x[32+q*4+3]=v.w; }
    }
    {
        const float* pp = g_pooled + row * 64;
        #pragma unroll
        for (int t = 0; t < 64; t++) {
            // literal: (x - mu) * rsqrt(var+eps) * gamma + beta
            float c = __fadd_rn(pp[t], -sMu[t]);
            x[48 + t] = fa(fm(fm(c, sR[t]), sG[t]), sBt[t]);
        }
    }

    float4 acc[8];
    #pragma unroll
    for (int kk = 0; kk < 8; kk++) acc[kk] = sb2[kk];

    #pragma unroll 2
    for (int j = 0; j < 64; j++) {
        float t0 = 0.f, t1 = 0.f, t2 = 0.f, t3 = 0.f;
        const float4* wrow = sW1t + j * 28;
        #pragma unroll
        for (int ii = 0; ii < 28; ii++) {
            float4 w = wrow[ii];
            t0 = fmaf(x[ii*4+0], w.x, t0);
            t1 = fmaf(x[ii*4+1], w.y, t1);
            t2 = fmaf(x[ii*4+2], w.z, t2);
            t3 = fmaf(x[ii*4+3], w.w, t3);
        }
        float t = fmaxf(sb1[j] + ((t0 + t1) + (t2 + t3)), 0.f);
        const float4* w2row = sW2 + j * 8;
        #pragma unroll
        for (int kk = 0; kk < 8; kk++) {
            float4 w = w2row[kk];
            acc[kk].x = fmaf(t, w.x, acc[kk].x);
            acc[kk].y = fmaf(t, w.y, acc[kk].y);
            acc[kk].z = fmaf(t, w.z, acc[kk].z);
            acc[kk].w = fmaf(t, w.w, acc[kk].w);
        }
    }

    float z = sb3;
    #pragma unroll
    for (int kk = 0; kk < 8; kk++) {
        float4 w = sW3[kk];
        z += fmaxf(acc[kk].x, 0.f) * w.x + fmaxf(acc[kk].y, 0.f) * w.y
           + fmaxf(acc[kk].z, 0.f) * w.z + fmaxf(acc[kk].w, 0.f) * w.w;
    }
    out[row] = 1.f / (1.f + expf(-z));
}

// ---------------------------------------------------------------------------
extern "C" void kernel_launch(void* const* d_in, const int* in_sizes, int n_in,
                              void* d_out, int out_size)
{
    const int* user_id  = (const int*)d_in[0];
    const int* movie_id = (const int*)d_in[1];
    const int* year     = (const int*)d_in[2];
    const int* ug       = (const int*)d_in[3];
    const int* urbv     = (const int*)d_in[4];
    const int* mg       = (const int*)d_in[5];
    const int* mt       = (const int*)d_in[6];
    const int* ug_c     = (const int*)d_in[7];
    const int* urb_c    = (const int*)d_in[8];
    const int* mg_c     = (const int*)d_in[9];
    const int* mt_c     = (const int*)d_in[10];
    const float* emb_user  = (const float*)d_in[11];
    const float* emb_movie = (const float*)d_in[12];
    const float* emb_tag   = (const float*)d_in[13];
    const float* emb_genre = (const float*)d_in[14];
    const float* emb_year  = (const float*)d_in[15];
    const float* at_movie  = (const float*)d_in[16];
    // d_in[17] = at_tagId   (unused by korder)
    // d_in[18] = at_genreId (unused by sum/max)
    const float* gamma = (const float*)d_in[19];
    const float* beta  = (const float*)d_in[20];
    const float* W1 = (const float*)d_in[21];
    const float* b1 = (const float*)d_in[22];
    const float* W2 = (const float*)d_in[23];
    const float* b2 = (const float*)d_in[24];
    const float* W3 = (const float*)d_in[25];
    const float* b3 = (const float*)d_in[26];
    int B = in_sizes[0];

    zero_stats_kernel<<<1, 128>>>();
    pool3_kernel<<<(B + 127) / 128, 128>>>(
        ug, urbv, mg, mt, ug_c, urb_c, mg_c, mt_c,
        emb_movie, emb_tag, emb_genre, at_movie, B);
    stats_kernel<<<256, 64>>>(B);
    bn_kernel<<<1, 64>>>(B);
    mlp_kernel<<<(B + 127) / 128, 128>>>(
        user_id, movie_id, year, emb_user, emb_movie, emb_year,
        gamma, beta, W1, b1, W2, b2, W3, b3, (float*)d_out, B);
}

// round 6
// speedup vs baseline: 2.6402x; 2.6402x over previous
#include <cuda_runtime.h>
#include <math.h>

#define MAXB 32768

__device__ float g_pooled[MAXB * 64];    // [B][4 features * 16 dims]
__device__ float g_stats[128];           // [0:64) sum, [64:128) sumsq
__device__ float g_mu[64];
__device__ float g_var[64];

__device__ __forceinline__ float fm(float a, float b) { return __fmul_rn(a, b); }
__device__ __forceinline__ float fa(float a, float b) { return __fadd_rn(a, b); }

__global__ void zero_stats_kernel() {
    if (threadIdx.x < 128) g_stats[threadIdx.x] = 0.f;
}

// ---------------------------------------------------------------------------
// Pooling: one thread per row, BIT-IDENTICAL arithmetic to the R5 passing
// version (same per-dim chains, same pos order, same intrinsics), but all
// embedding reads are float4 and the attention pass recomputes exp weights
// instead of storing av[50]/w[50] local arrays.
// ---------------------------------------------------------------------------
__global__ __launch_bounds__(128) void pool4_kernel(
    const int* __restrict__ ug, const int* __restrict__ urbv,
    const int* __restrict__ mg, const int* __restrict__ mt,
    const int* __restrict__ ug_c, const int* __restrict__ urb_c,
    const int* __restrict__ mg_c, const int* __restrict__ mt_c,
    const float* __restrict__ emb_movie, const float* __restrict__ emb_tag,
    const float* __restrict__ emb_genre, const float* __restrict__ at_movie,
    int B)
{
    int row = blockIdx.x * 128 + threadIdx.x;
    if (row >= B) return;
    float4* outp = reinterpret_cast<float4*>(g_pooled + row * 64);
    const float4* gen4 = reinterpret_cast<const float4*>(emb_genre);
    const float4* mov4 = reinterpret_cast<const float4*>(emb_movie);
    const float4* tag4 = reinterpret_cast<const float4*>(emb_tag);

    // ---- feature 0: 'sum', genre table ----
    {
        int cnt = ug_c[row];
        const int* idp = ug + row * 50;
        float4 p0 = {0,0,0,0}, p1 = {0,0,0,0}, p2 = {0,0,0,0}, p3 = {0,0,0,0};
        for (int pos = 0; pos < cnt; pos++) {
            int id = idp[pos] * 4;
            float4 e0 = gen4[id], e1 = gen4[id+1], e2 = gen4[id+2], e3 = gen4[id+3];
            p0.x=fa(p0.x,e0.x); p0.y=fa(p0.y,e0.y); p0.z=fa(p0.z,e0.z); p0.w=fa(p0.w,e0.w);
            p1.x=fa(p1.x,e1.x); p1.y=fa(p1.y,e1.y); p1.z=fa(p1.z,e1.z); p1.w=fa(p1.w,e1.w);
            p2.x=fa(p2.x,e2.x); p2.y=fa(p2.y,e2.y); p2.z=fa(p2.z,e2.z); p2.w=fa(p2.w,e2.w);
            p3.x=fa(p3.x,e3.x); p3.y=fa(p3.y,e3.y); p3.z=fa(p3.z,e3.z); p3.w=fa(p3.w,e3.w);
        }
        outp[0]=p0; outp[1]=p1; outp[2]=p2; outp[3]=p3;
    }
    // ---- feature 1: 'atten', movie table. Same math as R5 (max-subtracted
    //      softmax over all 50 incl. masked zeros); exp weights recomputed
    //      per pass instead of stored. ----
    {
        int cnt = urb_c[row];
        const int* idp = urbv + row * 50;
        float M = (cnt < 50) ? 0.f : -1e30f;
        for (int pos = 0; pos < cnt; pos++)
            M = fmaxf(M, at_movie[idp[pos]]);
        float den = fm((float)(50 - cnt), expf(-M));
        for (int pos = 0; pos < cnt; pos++)
            den = fa(den, expf(__fadd_rn(at_movie[idp[pos]], -M)));
        float invden = __fdiv_rn(1.f, den);
        float4 n0 = {0,0,0,0}, n1 = {0,0,0,0}, n2 = {0,0,0,0}, n3 = {0,0,0,0};
        for (int pos = 0; pos < cnt; pos++) {
            int id = idp[pos];
            float wv = fm(expf(__fadd_rn(at_movie[id], -M)), invden);
            int b = id * 4;
            float4 e0 = mov4[b], e1 = mov4[b+1], e2 = mov4[b+2], e3 = mov4[b+3];
            n0.x=fa(n0.x,fm(e0.x,wv)); n0.y=fa(n0.y,fm(e0.y,wv)); n0.z=fa(n0.z,fm(e0.z,wv)); n0.w=fa(n0.w,fm(e0.w,wv));
            n1.x=fa(n1.x,fm(e1.x,wv)); n1.y=fa(n1.y,fm(e1.y,wv)); n1.z=fa(n1.z,fm(e1.z,wv)); n1.w=fa(n1.w,fm(e1.w,wv));
            n2.x=fa(n2.x,fm(e2.x,wv)); n2.y=fa(n2.y,fm(e2.y,wv)); n2.z=fa(n2.z,fm(e2.z,wv)); n2.w=fa(n2.w,fm(e2.w,wv));
            n3.x=fa(n3.x,fm(e3.x,wv)); n3.y=fa(n3.y,fm(e3.y,wv)); n3.z=fa(n3.z,fm(e3.z,wv)); n3.w=fa(n3.w,fm(e3.w,wv));
        }
        outp[4]=n0; outp[5]=n1; outp[6]=n2; outp[7]=n3;
    }
    // ---- feature 2: 'max' (first argmax of per-position L2), genre table.
    //      l2 chain kept in exact d=0..15 sequential order. ----
    {
        int cnt = mg_c[row];
        const int* idp = mg + row * 50;
        int bidx = -1;
        float best = 0.f;
        for (int pos = 0; pos < cnt; pos++) {
            int b = idp[pos] * 4;
            float4 e0 = gen4[b], e1 = gen4[b+1], e2 = gen4[b+2], e3 = gen4[b+3];
            float l2 = 0.f;
            l2=fa(l2,fm(e0.x,e0.x)); l2=fa(l2,fm(e0.y,e0.y)); l2=fa(l2,fm(e0.z,e0.z)); l2=fa(l2,fm(e0.w,e0.w));
            l2=fa(l2,fm(e1.x,e1.x)); l2=fa(l2,fm(e1.y,e1.y)); l2=fa(l2,fm(e1.z,e1.z)); l2=fa(l2,fm(e1.w,e1.w));
            l2=fa(l2,fm(e2.x,e2.x)); l2=fa(l2,fm(e2.y,e2.y)); l2=fa(l2,fm(e2.z,e2.z)); l2=fa(l2,fm(e2.w,e2.w));
            l2=fa(l2,fm(e3.x,e3.x)); l2=fa(l2,fm(e3.y,e3.y)); l2=fa(l2,fm(e3.z,e3.z)); l2=fa(l2,fm(e3.w,e3.w));
            if (l2 > best) { best = l2; bidx = pos; }
        }
        if (bidx >= 0) {
            int b = idp[bidx] * 4;
            outp[8] = gen4[b]; outp[9] = gen4[b+1]; outp[10] = gen4[b+2]; outp[11] = gen4[b+3];
        } else {
            float4 z = {0,0,0,0};
            outp[8] = z; outp[9] = z; outp[10] = z; outp[11] = z;
        }
    }
    // ---- feature 3: 'korder', tag table. n2 chain in exact d order. ----
    {
        int cnt = mt_c[row];
        const int* idp = mt + row * 50;
        float4 s0={0,0,0,0}, s1={0,0,0,0}, s2={0,0,0,0}, s3={0,0,0,0};
        float4 q0={0,0,0,0}, q1={0,0,0,0}, q2={0,0,0,0}, q3={0,0,0,0};
        for (int pos = 0; pos < cnt; pos++) {
            int b = idp[pos] * 4;
            float4 e0 = tag4[b], e1 = tag4[b+1], e2 = tag4[b+2], e3 = tag4[b+3];
            s0.x=fa(s0.x,e0.x); q0.x=fa(q0.x,fm(e0.x,e0.x));
            s0.y=fa(s0.y,e0.y); q0.y=fa(q0.y,fm(e0.y,e0.y));
            s0.z=fa(s0.z,e0.z); q0.z=fa(q0.z,fm(e0.z,e0.z));
            s0.w=fa(s0.w,e0.w); q0.w=fa(q0.w,fm(e0.w,e0.w));
            s1.x=fa(s1.x,e1.x); q1.x=fa(q1.x,fm(e1.x,e1.x));
            s1.y=fa(s1.y,e1.y); q1.y=fa(q1.y,fm(e1.y,e1.y));
            s1.z=fa(s1.z,e1.z); q1.z=fa(q1.z,fm(e1.z,e1.z));
            s1.w=fa(s1.w,e1.w); q1.w=fa(q1.w,fm(e1.w,e1.w));
            s2.x=fa(s2.x,e2.x); q2.x=fa(q2.x,fm(e2.x,e2.x));
            s2.y=fa(s2.y,e2.y); q2.y=fa(q2.y,fm(e2.y,e2.y));
            s2.z=fa(s2.z,e2.z); q2.z=fa(q2.z,fm(e2.z,e2.z));
            s2.w=fa(s2.w,e2.w); q2.w=fa(q2.w,fm(e2.w,e2.w));
            s3.x=fa(s3.x,e3.x); q3.x=fa(q3.x,fm(e3.x,e3.x));
            s3.y=fa(s3.y,e3.y); q3.y=fa(q3.y,fm(e3.y,e3.y));
            s3.z=fa(s3.z,e3.z); q3.z=fa(q3.z,fm(e3.z,e3.z));
            s3.w=fa(s3.w,e3.w); q3.w=fa(q3.w,fm(e3.w,e3.w));
        }
        float4 v0, v1, v2, v3;
        v0.x=fm(0.5f,__fadd_rn(fm(s0.x,s0.x),-q0.x)); v0.y=fm(0.5f,__fadd_rn(fm(s0.y,s0.y),-q0.y));
        v0.z=fm(0.5f,__fadd_rn(fm(s0.z,s0.z),-q0.z)); v0.w=fm(0.5f,__fadd_rn(fm(s0.w,s0.w),-q0.w));
        v1.x=fm(0.5f,__fadd_rn(fm(s1.x,s1.x),-q1.x)); v1.y=fm(0.5f,__fadd_rn(fm(s1.y,s1.y),-q1.y));
        v1.z=fm(0.5f,__fadd_rn(fm(s1.z,s1.z),-q1.z)); v1.w=fm(0.5f,__fadd_rn(fm(s1.w,s1.w),-q1.w));
        v2.x=fm(0.5f,__fadd_rn(fm(s2.x,s2.x),-q2.x)); v2.y=fm(0.5f,__fadd_rn(fm(s2.y,s2.y),-q2.y));
        v2.z=fm(0.5f,__fadd_rn(fm(s2.z,s2.z),-q2.z)); v2.w=fm(0.5f,__fadd_rn(fm(s2.w,s2.w),-q2.w));
        v3.x=fm(0.5f,__fadd_rn(fm(s3.x,s3.x),-q3.x)); v3.y=fm(0.5f,__fadd_rn(fm(s3.y,s3.y),-q3.y));
        v3.z=fm(0.5f,__fadd_rn(fm(s3.z,s3.z),-q3.z)); v3.w=fm(0.5f,__fadd_rn(fm(s3.w,s3.w),-q3.w));
        float n2 = 0.f;
        n2=fa(n2,fm(v0.x,v0.x)); n2=fa(n2,fm(v0.y,v0.y)); n2=fa(n2,fm(v0.z,v0.z)); n2=fa(n2,fm(v0.w,v0.w));
        n2=fa(n2,fm(v1.x,v1.x)); n2=fa(n2,fm(v1.y,v1.y)); n2=fa(n2,fm(v1.z,v1.z)); n2=fa(n2,fm(v1.w,v1.w));
        n2=fa(n2,fm(v2.x,v2.x)); n2=fa(n2,fm(v2.y,v2.y)); n2=fa(n2,fm(v2.z,v2.z)); n2=fa(n2,fm(v2.w,v2.w));
        n2=fa(n2,fm(v3.x,v3.x)); n2=fa(n2,fm(v3.y,v3.y)); n2=fa(n2,fm(v3.z,v3.z)); n2=fa(n2,fm(v3.w,v3.w));
        float n = fmaxf(__fsqrt_rn(n2), 1e-12f);
        float invn = __fdiv_rn(1.f, n);
        v0.x=fm(v0.x,invn); v0.y=fm(v0.y,invn); v0.z=fm(v0.z,invn); v0.w=fm(v0.w,invn);
        v1.x=fm(v1.x,invn); v1.y=fm(v1.y,invn); v1.z=fm(v1.z,invn); v1.w=fm(v1.w,invn);
        v2.x=fm(v2.x,invn); v2.y=fm(v2.y,invn); v2.z=fm(v2.z,invn); v2.w=fm(v2.w,invn);
        v3.x=fm(v3.x,invn); v3.y=fm(v3.y,invn); v3.z=fm(v3.z,invn); v3.w=fm(v3.w,invn);
        outp[12]=v0; outp[13]=v1; outp[14]=v2; outp[15]=v3;
    }
}

// ---------------------------------------------------------------------------
__global__ void stats_kernel(int B) {
    int d = threadIdx.x;           // 0..63
    float s = 0.f, q = 0.f;
    for (int r = blockIdx.x; r < B; r += 256) {
        float v = g_pooled[r * 64 + d];
        s = fa(s, v);
        q = fa(q, fm(v, v));
    }
    atomicAdd(&g_stats[d], s);
    atomicAdd(&g_stats[64 + d], q);
}

__global__ void bn_kernel(int B) {
    int t = threadIdx.x;
    if (t >= 64) return;
    float invB = 1.f / (float)B;
    float mean = g_stats[t] * invB;
    float var  = g_stats[64 + t] * invB - mean * mean;
    g_mu[t] = mean;
    g_var[t] = var;
}

// ---------------------------------------------------------------------------
// MLP (unchanged from the passing R5 kernel).
// ---------------------------------------------------------------------------
__global__ __launch_bounds__(128) void mlp_kernel(
    const int* __restrict__ uid, const int* __restrict__ mid,
    const int* __restrict__ yr,
    const float* __restrict__ emb_user, const float* __restrict__ emb_movie,
    const float* __restrict__ emb_year,
    const float* __restrict__ gamma, const float* __restrict__ beta,
    const float* __restrict__ W1, const float* __restrict__ b1,
    const float* __restrict__ W2, const float* __restrict__ b2,
    const float* __restrict__ W3, const float* __restrict__ b3,
    float* __restrict__ out, int B)
{
    __shared__ float4 sW1t[64 * 28];   // transposed: [j][i/4]
    __shared__ float4 sW2[64 * 8];
    __shared__ float  sb1[64], sMu[64], sR[64], sG[64], sBt[64];
    __shared__ float4 sb2[8], sW3[8];
    __shared__ float  sb3;
    int tid = threadIdx.x;
    for (int idx = tid; idx < 64 * 112; idx += 128) {
        int j = idx / 112, i = idx % 112;
        reinterpret_cast<float*>(sW1t)[j * 112 + i] = W1[i * 64 + j];
    }
    for (int idx = tid; idx < 64 * 8; idx += 128)
        sW2[idx] = reinterpret_cast<const float4*>(W2)[idx];
    if (tid < 64) {
        sb1[tid] = b1[tid];
        sMu[tid] = g_mu[tid];
        sR[tid]  = rsqrtf(__fadd_rn(g_var[tid], 1e-5f));
        sG[tid]  = gamma[tid];
        sBt[tid] = beta[tid];
    }
    if (tid < 8) {
        sb2[tid] = reinterpret_cast<const float4*>(b2)[tid];
        sW3[tid] = reinterpret_cast<const float4*>(W3)[tid];
    }
    if (tid == 0) sb3 = b3[0];
    __syncthreads();

    int row = blockIdx.x * 128 + tid;
    if (row >= B) return;

    float x[112];
    {
        const float4* p4 = reinterpret_cast<const float4*>(emb_user) + uid[row] * 4;
        #pragma unroll
        for (int q = 0; q < 4; q++) { float4 v = p4[q];
            x[q*4+0]=v.x; x[q*4+1]=v.y; x[q*4+2]=v.z; x[q*4+3]=v.w; }
    }
    {
        const float4* p4 = reinterpret_cast<const float4*>(emb_movie) + mid[row] * 4;
        #pragma unroll
        for (int q = 0; q < 4; q++) { float4 v = p4[q];
            x[16+q*4+0]=v.x; x[16+q*4+1]=v.y; x[16+q*4+2]=v.z; x[16+q*4+3]=v.w; }
    }
    {
        const float4* p4 = reinterpret_cast<const float4*>(emb_year) + yr[row] * 4;
        #pragma unroll
        for (int q = 0; q < 4; q++) { float4 v = p4[q];
            x[32+q*4+0]=v.x; x[32+q*4+1]=v.y; x[32+q*4+2]=v.z; x[32+q*4+3]=v.w; }
    }
    {
        const float* pp = g_pooled + row * 64;
        #pragma unroll
        for (int t = 0; t < 64; t++) {
            float c = __fadd_rn(pp[t], -sMu[t]);
            x[48 + t] = fa(fm(fm(c, sR[t]), sG[t]), sBt[t]);
        }
    }

    float4 acc[8];
    #pragma unroll
    for (int kk = 0; kk < 8; kk++) acc[kk] = sb2[kk];

    #pragma unroll 2
    for (int j = 0; j < 64; j++) {
        float t0 = 0.f, t1 = 0.f, t2 = 0.f, t3 = 0.f;
        const float4* wrow = sW1t + j * 28;
        #pragma unroll
        for (int ii = 0; ii < 28; ii++) {
            float4 w = wrow[ii];
            t0 = fmaf(x[ii*4+0], w.x, t0);
            t1 = fmaf(x[ii*4+1], w.y, t1);
            t2 = fmaf(x[ii*4+2], w.z, t2);
            t3 = fmaf(x[ii*4+3], w.w, t3);
        }
        float t = fmaxf(sb1[j] + ((t0 + t1) + (t2 + t3)), 0.f);
        const float4* w2row = sW2 + j * 8;
        #pragma unroll
        for (int kk = 0; kk < 8; kk++) {
            float4 w = w2row[kk];
            acc[kk].x = fmaf(t, w.x, acc[kk].x);
            acc[kk].y = fmaf(t, w.y, acc[kk].y);
            acc[kk].z = fmaf(t, w.z, acc[kk].z);
            acc[kk].w = fmaf(t, w.w, acc[kk].w);
        }
    }

    float z = sb3;
    #pragma unroll
    for (int kk = 0; kk < 8; kk++) {
        float4 w = sW3[kk];
        z += fmaxf(acc[kk].x, 0.f) * w.x + fmaxf(acc[kk].y, 0.f) * w.y
           + fmaxf(acc[kk].z, 0.f) * w.z + fmaxf(acc[kk].w, 0.f) * w.w;
    }
    out[row] = 1.f / (1.f + expf(-z));
}

// ---------------------------------------------------------------------------
extern "C" void kernel_launch(void* const* d_in, const int* in_sizes, int n_in,
                              void* d_out, int out_size)
{
    const int* user_id  = (const int*)d_in[0];
    const int* movie_id = (const int*)d_in[1];
    const int* year     = (const int*)d_in[2];
    const int* ug       = (const int*)d_in[3];
    const int* urbv     = (const int*)d_in[4];
    const int* mg       = (const int*)d_in[5];
    const int* mt       = (const int*)d_in[6];
    const int* ug_c     = (const int*)d_in[7];
    const int* urb_c    = (const int*)d_in[8];
    const int* mg_c     = (const int*)d_in[9];
    const int* mt_c     = (const int*)d_in[10];
    const float* emb_user  = (const float*)d_in[11];
    const float* emb_movie = (const float*)d_in[12];
    const float* emb_tag   = (const float*)d_in[13];
    const float* emb_genre = (const float*)d_in[14];
    const float* emb_year  = (const float*)d_in[15];
    const float* at_movie  = (const float*)d_in[16];
    // d_in[17] = at_tagId   (unused by korder)
    // d_in[18] = at_genreId (unused by sum/max)
    const float* gamma = (const float*)d_in[19];
    const float* beta  = (const float*)d_in[20];
    const float* W1 = (const float*)d_in[21];
    const float* b1 = (const float*)d_in[22];
    const float* W2 = (const float*)d_in[23];
    const float* b2 = (const float*)d_in[24];
    const float* W3 = (const float*)d_in[25];
    const float* b3 = (const float*)d_in[26];
    int B = in_sizes[0];

    zero_stats_kernel<<<1, 128>>>();
    pool4_kernel<<<(B + 127) / 128, 128>>>(
        ug, urbv, mg, mt, ug_c, urb_c, mg_c, mt_c,
        emb_movie, emb_tag, emb_genre, at_movie, B);
    stats_kernel<<<256, 64>>>(B);
    bn_kernel<<<1, 64>>>(B);
    mlp_kernel<<<(B + 127) / 128, 128>>>(
        user_id, movie_id, year, emb_user, emb_movie, emb_year,
        gamma, beta, W1, b1, W2, b2, W3, b3, (float*)d_out, B);
}

// round 8
// speedup vs baseline: 3.0172x; 1.1428x over previous
#include <cuda_runtime.h>
#include <math.h>

#define MAXB 32768

__device__ float g_pooled[MAXB * 64];    // [B][4 features * 16 dims]
__device__ float g_part[256 * 128];      // per-block stat partials
__device__ float g_mu[64];
__device__ float g_var[64];

__device__ __forceinline__ float fm(float a, float b) { return __fmul_rn(a, b); }
__device__ __forceinline__ float fa(float a, float b) { return __fadd_rn(a, b); }

// ---------------------------------------------------------------------------
// Pooling: one thread per (row, feature). blockIdx.y = feature, so every
// warp is feature-uniform. Each feature's scalar arithmetic chain is
// byte-identical to the passing R6 kernel.
// ---------------------------------------------------------------------------
__global__ __launch_bounds__(128) void pool5_kernel(
    const int* __restrict__ ug, const int* __restrict__ urbv,
    const int* __restrict__ mg, const int* __restrict__ mt,
    const int* __restrict__ ug_c, const int* __restrict__ urb_c,
    const int* __restrict__ mg_c, const int* __restrict__ mt_c,
    const float* __restrict__ emb_movie, const float* __restrict__ emb_tag,
    const float* __restrict__ emb_genre, const float* __restrict__ at_movie,
    int B)
{
    int row = blockIdx.x * 128 + threadIdx.x;
    if (row >= B) return;
    float4* outp = reinterpret_cast<float4*>(g_pooled + row * 64);
    const float4* gen4 = reinterpret_cast<const float4*>(emb_genre);
    const float4* mov4 = reinterpret_cast<const float4*>(emb_movie);
    const float4* tag4 = reinterpret_cast<const float4*>(emb_tag);

    switch (blockIdx.y) {
    case 0: {  // ---- 'sum', genre table ----
        int cnt = ug_c[row];
        const int* idp = ug + row * 50;
        float4 p0 = {0,0,0,0}, p1 = {0,0,0,0}, p2 = {0,0,0,0}, p3 = {0,0,0,0};
        for (int pos = 0; pos < cnt; pos++) {
            int id = idp[pos] * 4;
            float4 e0 = gen4[id], e1 = gen4[id+1], e2 = gen4[id+2], e3 = gen4[id+3];
            p0.x=fa(p0.x,e0.x); p0.y=fa(p0.y,e0.y); p0.z=fa(p0.z,e0.z); p0.w=fa(p0.w,e0.w);
            p1.x=fa(p1.x,e1.x); p1.y=fa(p1.y,e1.y); p1.z=fa(p1.z,e1.z); p1.w=fa(p1.w,e1.w);
            p2.x=fa(p2.x,e2.x); p2.y=fa(p2.y,e2.y); p2.z=fa(p2.z,e2.z); p2.w=fa(p2.w,e2.w);
            p3.x=fa(p3.x,e3.x); p3.y=fa(p3.y,e3.y); p3.z=fa(p3.z,e3.z); p3.w=fa(p3.w,e3.w);
        }
        outp[0]=p0; outp[1]=p1; outp[2]=p2; outp[3]=p3;
        break;
    }
    case 1: {  // ---- 'atten', movie table (max-subtracted softmax over 50) ----
        int cnt = urb_c[row];
        const int* idp = urbv + row * 50;
        float M = (cnt < 50) ? 0.f : -1e30f;
        for (int pos = 0; pos < cnt; pos++)
            M = fmaxf(M, at_movie[idp[pos]]);
        float den = fm((float)(50 - cnt), expf(-M));
        for (int pos = 0; pos < cnt; pos++)
            den = fa(den, expf(__fadd_rn(at_movie[idp[pos]], -M)));
        float invden = __fdiv_rn(1.f, den);
        float4 n0 = {0,0,0,0}, n1 = {0,0,0,0}, n2 = {0,0,0,0}, n3 = {0,0,0,0};
        for (int pos = 0; pos < cnt; pos++) {
            int id = idp[pos];
            float wv = fm(expf(__fadd_rn(at_movie[id], -M)), invden);
            int b = id * 4;
            float4 e0 = mov4[b], e1 = mov4[b+1], e2 = mov4[b+2], e3 = mov4[b+3];
            n0.x=fa(n0.x,fm(e0.x,wv)); n0.y=fa(n0.y,fm(e0.y,wv)); n0.z=fa(n0.z,fm(e0.z,wv)); n0.w=fa(n0.w,fm(e0.w,wv));
            n1.x=fa(n1.x,fm(e1.x,wv)); n1.y=fa(n1.y,fm(e1.y,wv)); n1.z=fa(n1.z,fm(e1.z,wv)); n1.w=fa(n1.w,fm(e1.w,wv));
            n2.x=fa(n2.x,fm(e2.x,wv)); n2.y=fa(n2.y,fm(e2.y,wv)); n2.z=fa(n2.z,fm(e2.z,wv)); n2.w=fa(n2.w,fm(e2.w,wv));
            n3.x=fa(n3.x,fm(e3.x,wv)); n3.y=fa(n3.y,fm(e3.y,wv)); n3.z=fa(n3.z,fm(e3.z,wv)); n3.w=fa(n3.w,fm(e3.w,wv));
        }
        outp[4]=n0; outp[5]=n1; outp[6]=n2; outp[7]=n3;
        break;
    }
    case 2: {  // ---- 'max' (first argmax of per-position L2), genre table ----
        int cnt = mg_c[row];
        const int* idp = mg + row * 50;
        int bidx = -1;
        float best = 0.f;
        for (int pos = 0; pos < cnt; pos++) {
            int b = idp[pos] * 4;
            float4 e0 = gen4[b], e1 = gen4[b+1], e2 = gen4[b+2], e3 = gen4[b+3];
            float l2 = 0.f;
            l2=fa(l2,fm(e0.x,e0.x)); l2=fa(l2,fm(e0.y,e0.y)); l2=fa(l2,fm(e0.z,e0.z)); l2=fa(l2,fm(e0.w,e0.w));
            l2=fa(l2,fm(e1.x,e1.x)); l2=fa(l2,fm(e1.y,e1.y)); l2=fa(l2,fm(e1.z,e1.z)); l2=fa(l2,fm(e1.w,e1.w));
            l2=fa(l2,fm(e2.x,e2.x)); l2=fa(l2,fm(e2.y,e2.y)); l2=fa(l2,fm(e2.z,e2.z)); l2=fa(l2,fm(e2.w,e2.w));
            l2=fa(l2,fm(e3.x,e3.x)); l2=fa(l2,fm(e3.y,e3.y)); l2=fa(l2,fm(e3.z,e3.z)); l2=fa(l2,fm(e3.w,e3.w));
            if (l2 > best) { best = l2; bidx = pos; }
        }
        if (bidx >= 0) {
            int b = idp[bidx] * 4;
            outp[8] = gen4[b]; outp[9] = gen4[b+1]; outp[10] = gen4[b+2]; outp[11] = gen4[b+3];
        } else {
            float4 z = {0,0,0,0};
            outp[8] = z; outp[9] = z; outp[10] = z; outp[11] = z;
        }
        break;
    }
    default: {  // ---- 'korder', tag table ----
        int cnt = mt_c[row];
        const int* idp = mt + row * 50;
        float4 s0={0,0,0,0}, s1={0,0,0,0}, s2={0,0,0,0}, s3={0,0,0,0};
        float4 q0={0,0,0,0}, q1={0,0,0,0}, q2={0,0,0,0}, q3={0,0,0,0};
        for (int pos = 0; pos < cnt; pos++) {
            int b = idp[pos] * 4;
            float4 e0 = tag4[b], e1 = tag4[b+1], e2 = tag4[b+2], e3 = tag4[b+3];
            s0.x=fa(s0.x,e0.x); q0.x=fa(q0.x,fm(e0.x,e0.x));
            s0.y=fa(s0.y,e0.y); q0.y=fa(q0.y,fm(e0.y,e0.y));
            s0.z=fa(s0.z,e0.z); q0.z=fa(q0.z,fm(e0.z,e0.z));
            s0.w=fa(s0.w,e0.w); q0.w=fa(q0.w,fm(e0.w,e0.w));
            s1.x=fa(s1.x,e1.x); q1.x=fa(q1.x,fm(e1.x,e1.x));
            s1.y=fa(s1.y,e1.y); q1.y=fa(q1.y,fm(e1.y,e1.y));
            s1.z=fa(s1.z,e1.z); q1.z=fa(q1.z,fm(e1.z,e1.z));
            s1.w=fa(s1.w,e1.w); q1.w=fa(q1.w,fm(e1.w,e1.w));
            s2.x=fa(s2.x,e2.x); q2.x=fa(q2.x,fm(e2.x,e2.x));
            s2.y=fa(s2.y,e2.y); q2.y=fa(q2.y,fm(e2.y,e2.y));
            s2.z=fa(s2.z,e2.z); q2.z=fa(q2.z,fm(e2.z,e2.z));
            s2.w=fa(s2.w,e2.w); q2.w=fa(q2.w,fm(e2.w,e2.w));
            s3.x=fa(s3.x,e3.x); q3.x=fa(q3.x,fm(e3.x,e3.x));
            s3.y=fa(s3.y,e3.y); q3.y=fa(q3.y,fm(e3.y,e3.y));
            s3.z=fa(s3.z,e3.z); q3.z=fa(q3.z,fm(e3.z,e3.z));
            s3.w=fa(s3.w,e3.w); q3.w=fa(q3.w,fm(e3.w,e3.w));
        }
        float4 v0, v1, v2, v3;
        v0.x=fm(0.5f,__fadd_rn(fm(s0.x,s0.x),-q0.x)); v0.y=fm(0.5f,__fadd_rn(fm(s0.y,s0.y),-q0.y));
        v0.z=fm(0.5f,__fadd_rn(fm(s0.z,s0.z),-q0.z)); v0.w=fm(0.5f,__fadd_rn(fm(s0.w,s0.w),-q0.w));
        v1.x=fm(0.5f,__fadd_rn(fm(s1.x,s1.x),-q1.x)); v1.y=fm(0.5f,__fadd_rn(fm(s1.y,s1.y),-q1.y));
        v1.z=fm(0.5f,__fadd_rn(fm(s1.z,s1.z),-q1.z)); v1.w=fm(0.5f,__fadd_rn(fm(s1.w,s1.w),-q1.w));
        v2.x=fm(0.5f,__fadd_rn(fm(s2.x,s2.x),-q2.x)); v2.y=fm(0.5f,__fadd_rn(fm(s2.y,s2.y),-q2.y));
        v2.z=fm(0.5f,__fadd_rn(fm(s2.z,s2.z),-q2.z)); v2.w=fm(0.5f,__fadd_rn(fm(s2.w,s2.w),-q2.w));
        v3.x=fm(0.5f,__fadd_rn(fm(s3.x,s3.x),-q3.x)); v3.y=fm(0.5f,__fadd_rn(fm(s3.y,s3.y),-q3.y));
        v3.z=fm(0.5f,__fadd_rn(fm(s3.z,s3.z),-q3.z)); v3.w=fm(0.5f,__fadd_rn(fm(s3.w,s3.w),-q3.w));
        float n2 = 0.f;
        n2=fa(n2,fm(v0.x,v0.x)); n2=fa(n2,fm(v0.y,v0.y)); n2=fa(n2,fm(v0.z,v0.z)); n2=fa(n2,fm(v0.w,v0.w));
        n2=fa(n2,fm(v1.x,v1.x)); n2=fa(n2,fm(v1.y,v1.y)); n2=fa(n2,fm(v1.z,v1.z)); n2=fa(n2,fm(v1.w,v1.w));
        n2=fa(n2,fm(v2.x,v2.x)); n2=fa(n2,fm(v2.y,v2.y)); n2=fa(n2,fm(v2.z,v2.z)); n2=fa(n2,fm(v2.w,v2.w));
        n2=fa(n2,fm(v3.x,v3.x)); n2=fa(n2,fm(v3.y,v3.y)); n2=fa(n2,fm(v3.z,v3.z)); n2=fa(n2,fm(v3.w,v3.w));
        float n = fmaxf(__fsqrt_rn(n2), 1e-12f);
        float invn = __fdiv_rn(1.f, n);
        v0.x=fm(v0.x,invn); v0.y=fm(v0.y,invn); v0.z=fm(v0.z,invn); v0.w=fm(v0.w,invn);
        v1.x=fm(v1.x,invn); v1.y=fm(v1.y,invn); v1.z=fm(v1.z,invn); v1.w=fm(v1.w,invn);
        v2.x=fm(v2.x,invn); v2.y=fm(v2.y,invn); v2.z=fm(v2.z,invn); v2.w=fm(v2.w,invn);
        v3.x=fm(v3.x,invn); v3.y=fm(v3.y,invn); v3.z=fm(v3.z,invn); v3.w=fm(v3.w,invn);
        outp[12]=v0; outp[13]=v1; outp[14]=v2; outp[15]=v3;
        break;
    }
    }
}

// ---------------------------------------------------------------------------
// BN statistics: deterministic per-block partials (no atomics, no zeroing).
// ---------------------------------------------------------------------------
__global__ void stats_kernel(int B) {
    int d = threadIdx.x;           // 0..63
    float s = 0.f, q = 0.f;
    for (int r = blockIdx.x; r < B; r += 256) {
        float v = g_pooled[r * 64 + d];
        s = fa(s, v);
        q = fa(q, fm(v, v));
    }
    g_part[blockIdx.x * 128 + d] = s;
    g_part[blockIdx.x * 128 + 64 + d] = q;
}

__global__ void bn_kernel(int B) {
    int t = threadIdx.x;
    if (t >= 64) return;
    float s = 0.f, q = 0.f;
    for (int b = 0; b < 256; b++) {
        s = fa(s, g_part[b * 128 + t]);
        q = fa(q, g_part[b * 128 + 64 + t]);
    }
    float invB = 1.f / (float)B;
    float mean = s * invB;
    float var  = q * invB - mean * mean;
    g_mu[t] = mean;
    g_var[t] = var;
}

// ---------------------------------------------------------------------------
// MLP (unchanged from the passing R6 kernel).
// ---------------------------------------------------------------------------
__global__ __launch_bounds__(128) void mlp_kernel(
    const int* __restrict__ uid, const int* __restrict__ mid,
    const int* __restrict__ yr,
    const float* __restrict__ emb_user, const float* __restrict__ emb_movie,
    const float* __restrict__ emb_year,
    const float* __restrict__ gamma, const float* __restrict__ beta,
    const float* __restrict__ W1, const float* __restrict__ b1,
    const float* __restrict__ W2, const float* __restrict__ b2,
    const float* __restrict__ W3, const float* __restrict__ b3,
    float* __restrict__ out, int B)
{
    __shared__ float4 sW1t[64 * 28];   // transposed: [j][i/4]
    __shared__ float4 sW2[64 * 8];
    __shared__ float  sb1[64], sMu[64], sR[64], sG[64], sBt[64];
    __shared__ float4 sb2[8], sW3[8];
    __shared__ float  sb3;
    int tid = threadIdx.x;
    for (int idx = tid; idx < 64 * 112; idx += 128) {
        int j = idx / 112, i = idx % 112;
        reinterpret_cast<float*>(sW1t)[j * 112 + i] = W1[i * 64 + j];
    }
    for (int idx = tid; idx < 64 * 8; idx += 128)
        sW2[idx] = reinterpret_cast<const float4*>(W2)[idx];
    if (tid < 64) {
        sb1[tid] = b1[tid];
        sMu[tid] = g_mu[tid];
        sR[tid]  = rsqrtf(__fadd_rn(g_var[tid], 1e-5f));
        sG[tid]  = gamma[tid];
        sBt[tid] = beta[tid];
    }
    if (tid < 8) {
        sb2[tid] = reinterpret_cast<const float4*>(b2)[tid];
        sW3[tid] = reinterpret_cast<const float4*>(W3)[tid];
    }
    if (tid == 0) sb3 = b3[0];
    __syncthreads();

    int row = blockIdx.x * 128 + tid;
    if (row >= B) return;

    float x[112];
    {
        const float4* p4 = reinterpret_cast<const float4*>(emb_user) + uid[row] * 4;
        #pragma unroll
        for (int q = 0; q < 4; q++) { float4 v = p4[q];
            x[q*4+0]=v.x; x[q*4+1]=v.y; x[q*4+2]=v.z; x[q*4+3]=v.w; }
    }
    {
        const float4* p4 = reinterpret_cast<const float4*>(emb_movie) + mid[row] * 4;
        #pragma unroll
        for (int q = 0; q < 4; q++) { float4 v = p4[q];
            x[16+q*4+0]=v.x; x[16+q*4+1]=v.y; x[16+q*4+2]=v.z; x[16+q*4+3]=v.w; }
    }
    {
        const float4* p4 = reinterpret_cast<const float4*>(emb_year) + yr[row] * 4;
        #pragma unroll
        for (int q = 0; q < 4; q++) { float4 v = p4[q];
            x[32+q*4+0]=v.x; x[32+q*4+1]=v.y; x[32+q*4+2]=v.z; x[32+q*4+3]=v.w; }
    }
    {
        const float* pp = g_pooled + row * 64;
        #pragma unroll
        for (int t = 0; t < 64; t++) {
            float c = __fadd_rn(pp[t], -sMu[t]);
            x[48 + t] = fa(fm(fm(c, sR[t]), sG[t]), sBt[t]);
        }
    }

    float4 acc[8];
    #pragma unroll
    for (int kk = 0; kk < 8; kk++) acc[kk] = sb2[kk];

    #pragma unroll 2
    for (int j = 0; j < 64; j++) {
        float t0 = 0.f, t1 = 0.f, t2 = 0.f, t3 = 0.f;
        const float4* wrow = sW1t + j * 28;
        #pragma unroll
        for (int ii = 0; ii < 28; ii++) {
            float4 w = wrow[ii];
            t0 = fmaf(x[ii*4+0], w.x, t0);
            t1 = fmaf(x[ii*4+1], w.y, t1);
            t2 = fmaf(x[ii*4+2], w.z, t2);
            t3 = fmaf(x[ii*4+3], w.w, t3);
        }
        float t = fmaxf(sb1[j] + ((t0 + t1) + (t2 + t3)), 0.f);
        const float4* w2row = sW2 + j * 8;
        #pragma unroll
        for (int kk = 0; kk < 8; kk++) {
            float4 w = w2row[kk];
            acc[kk].x = fmaf(t, w.x, acc[kk].x);
            acc[kk].y = fmaf(t, w.y, acc[kk].y);
            acc[kk].z = fmaf(t, w.z, acc[kk].z);
            acc[kk].w = fmaf(t, w.w, acc[kk].w);
        }
    }

    float z = sb3;
    #pragma unroll
    for (int kk = 0; kk < 8; kk++) {
        float4 w = sW3[kk];
        z += fmaxf(acc[kk].x, 0.f) * w.x + fmaxf(acc[kk].y, 0.f) * w.y
           + fmaxf(acc[kk].z, 0.f) * w.z + fmaxf(acc[kk].w, 0.f) * w.w;
    }
    out[row] = 1.f / (1.f + expf(-z));
}

// ---------------------------------------------------------------------------
extern "C" void kernel_launch(void* const* d_in, const int* in_sizes, int n_in,
                              void* d_out, int out_size)
{
    const int* user_id  = (const int*)d_in[0];
    const int* movie_id = (const int*)d_in[1];
    const int* year     = (const int*)d_in[2];
    const int* ug       = (const int*)d_in[3];
    const int* urbv     = (const int*)d_in[4];
    const int* mg       = (const int*)d_in[5];
    const int* mt       = (const int*)d_in[6];
    const int* ug_c     = (const int*)d_in[7];
    const int* urb_c    = (const int*)d_in[8];
    const int* mg_c     = (const int*)d_in[9];
    const int* mt_c     = (const int*)d_in[10];
    const float* emb_user  = (const float*)d_in[11];
    const float* emb_movie = (const float*)d_in[12];
    const float* emb_tag   = (const float*)d_in[13];
    const float* emb_genre = (const float*)d_in[14];
    const float* emb_year  = (const float*)d_in[15];
    const float* at_movie  = (const float*)d_in[16];
    // d_in[17] = at_tagId   (unused by korder)
    // d_in[18] = at_genreId (unused by sum/max)
    const float* gamma = (const float*)d_in[19];
    const float* beta  = (const float*)d_in[20];
    const float* W1 = (const float*)d_in[21];
    const float* b1 = (const float*)d_in[22];
    const float* W2 = (const float*)d_in[23];
    const float* b2 = (const float*)d_in[24];
    const float* W3 = (const float*)d_in[25];
    const float* b3 = (const float*)d_in[26];
    int B = in_sizes[0];

    dim3 pgrid((B + 127) / 128, 4);
    pool5_kernel<<<pgrid, 128>>>(
        ug, urbv, mg, mt, ug_c, urb_c, mg_c, mt_c,
        emb_movie, emb_tag, emb_genre, at_movie, B);
    stats_kernel<<<256, 64>>>(B);
    bn_kernel<<<1, 64>>>(B);
    mlp_kernel<<<(B + 127) / 128, 128>>>(
        user_id, movie_id, year, emb_user, emb_movie, emb_year,
        gamma, beta, W1, b1, W2, b2, W3, b3, (float*)d_out, B);
}

// round 9
// speedup vs baseline: 3.1460x; 1.0427x over previous
#include <cuda_runtime.h>
#include <math.h>

#define MAXB 32768

__device__ float g_pooled[MAXB * 64];    // [B][4 features * 16 dims]
__device__ float g_part[256 * 128];      // per-block stat partials
__device__ float g_mu[64];
__device__ float g_var[64];

__device__ __forceinline__ float fm(float a, float b) { return __fmul_rn(a, b); }
__device__ __forceinline__ float fa(float a, float b) { return __fadd_rn(a, b); }

// ---------------------------------------------------------------------------
// Pooling: blockIdx.y = feature (warp-uniform).
//   f0 ('sum',   genre): 1 thread/row, genre table in smem (same values).
//   f1 ('atten', movie): 2 threads/row, dims 0-7 / 8-15 (per-dim chains exact).
//   f2 ('max',   genre): 1 thread/row, per-id L2 precomputed once in smem with
//                        the exact 16-term chain (bitwise-equal values).
//   f3 ('korder', tag):  2 threads/row; cross-dim n2 rebuilt bit-exactly by
//                        exchanging v-halves and evaluating the full chain.
// ---------------------------------------------------------------------------
__global__ __launch_bounds__(128) void pool6_kernel(
    const int* __restrict__ ug, const int* __restrict__ urbv,
    const int* __restrict__ mg, const int* __restrict__ mt,
    const int* __restrict__ ug_c, const int* __restrict__ urb_c,
    const int* __restrict__ mg_c, const int* __restrict__ mt_c,
    const float* __restrict__ emb_movie, const float* __restrict__ emb_tag,
    const float* __restrict__ emb_genre, const float* __restrict__ at_movie,
    int B)
{
    __shared__ float4 s_gen[30 * 4];
    __shared__ float  s_l2[30];
    int tid = threadIdx.x;
    int feat = blockIdx.y;

    if (feat == 0 || feat == 2) {
        if (tid < 120) s_gen[tid] = reinterpret_cast<const float4*>(emb_genre)[tid];
        __syncthreads();
        if (feat == 2) {
            if (tid < 30) {
                float4 e0 = s_gen[tid*4], e1 = s_gen[tid*4+1],
                       e2 = s_gen[tid*4+2], e3 = s_gen[tid*4+3];
                float l2 = 0.f;
                l2=fa(l2,fm(e0.x,e0.x)); l2=fa(l2,fm(e0.y,e0.y)); l2=fa(l2,fm(e0.z,e0.z)); l2=fa(l2,fm(e0.w,e0.w));
                l2=fa(l2,fm(e1.x,e1.x)); l2=fa(l2,fm(e1.y,e1.y)); l2=fa(l2,fm(e1.z,e1.z)); l2=fa(l2,fm(e1.w,e1.w));
                l2=fa(l2,fm(e2.x,e2.x)); l2=fa(l2,fm(e2.y,e2.y)); l2=fa(l2,fm(e2.z,e2.z)); l2=fa(l2,fm(e2.w,e2.w));
                l2=fa(l2,fm(e3.x,e3.x)); l2=fa(l2,fm(e3.y,e3.y)); l2=fa(l2,fm(e3.z,e3.z)); l2=fa(l2,fm(e3.w,e3.w));
                s_l2[tid] = l2;
            }
            __syncthreads();
        }
    }

    int gtid = blockIdx.x * 128 + tid;
    const float4* mov4 = reinterpret_cast<const float4*>(emb_movie);
    const float4* tag4 = reinterpret_cast<const float4*>(emb_tag);

    if (feat == 0) {
        int row = gtid;
        if (row >= B) return;
        float4* outp = reinterpret_cast<float4*>(g_pooled + row * 64);
        int cnt = ug_c[row];
        const int* idp = ug + row * 50;
        float4 p0 = {0,0,0,0}, p1 = {0,0,0,0}, p2 = {0,0,0,0}, p3 = {0,0,0,0};
        for (int pos = 0; pos < cnt; pos++) {
            int id = idp[pos] * 4;
            float4 e0 = s_gen[id], e1 = s_gen[id+1], e2 = s_gen[id+2], e3 = s_gen[id+3];
            p0.x=fa(p0.x,e0.x); p0.y=fa(p0.y,e0.y); p0.z=fa(p0.z,e0.z); p0.w=fa(p0.w,e0.w);
            p1.x=fa(p1.x,e1.x); p1.y=fa(p1.y,e1.y); p1.z=fa(p1.z,e1.z); p1.w=fa(p1.w,e1.w);
            p2.x=fa(p2.x,e2.x); p2.y=fa(p2.y,e2.y); p2.z=fa(p2.z,e2.z); p2.w=fa(p2.w,e2.w);
            p3.x=fa(p3.x,e3.x); p3.y=fa(p3.y,e3.y); p3.z=fa(p3.z,e3.z); p3.w=fa(p3.w,e3.w);
        }
        outp[0]=p0; outp[1]=p1; outp[2]=p2; outp[3]=p3;
    } else if (feat == 1) {
        int row = gtid >> 1, half = gtid & 1;
        if (row >= B) return;
        float4* outp = reinterpret_cast<float4*>(g_pooled + row * 64);
        int cnt = urb_c[row];
        const int* idp = urbv + row * 50;
        float M = (cnt < 50) ? 0.f : -1e30f;
        for (int pos = 0; pos < cnt; pos++)
            M = fmaxf(M, at_movie[idp[pos]]);
        float den = fm((float)(50 - cnt), expf(-M));
        for (int pos = 0; pos < cnt; pos++)
            den = fa(den, expf(__fadd_rn(at_movie[idp[pos]], -M)));
        float invden = __fdiv_rn(1.f, den);
        float4 n0 = {0,0,0,0}, n1 = {0,0,0,0};
        for (int pos = 0; pos < cnt; pos++) {
            int id = idp[pos];
            float wv = fm(expf(__fadd_rn(at_movie[id], -M)), invden);
            int b = id * 4 + half * 2;
            float4 e0 = mov4[b], e1 = mov4[b+1];
            n0.x=fa(n0.x,fm(e0.x,wv)); n0.y=fa(n0.y,fm(e0.y,wv)); n0.z=fa(n0.z,fm(e0.z,wv)); n0.w=fa(n0.w,fm(e0.w,wv));
            n1.x=fa(n1.x,fm(e1.x,wv)); n1.y=fa(n1.y,fm(e1.y,wv)); n1.z=fa(n1.z,fm(e1.z,wv)); n1.w=fa(n1.w,fm(e1.w,wv));
        }
        outp[4 + half*2] = n0; outp[5 + half*2] = n1;
    } else if (feat == 2) {
        int row = gtid;
        if (row >= B) return;
        float4* outp = reinterpret_cast<float4*>(g_pooled + row * 64);
        int cnt = mg_c[row];
        const int* idp = mg + row * 50;
        int bidx = -1;
        float best = 0.f;
        for (int pos = 0; pos < cnt; pos++) {
            float l2 = s_l2[idp[pos]];
            if (l2 > best) { best = l2; bidx = pos; }
        }
        if (bidx >= 0) {
            int b = idp[bidx] * 4;
            outp[8] = s_gen[b]; outp[9] = s_gen[b+1]; outp[10] = s_gen[b+2]; outp[11] = s_gen[b+3];
        } else {
            float4 z = {0,0,0,0};
            outp[8] = z; outp[9] = z; outp[10] = z; outp[11] = z;
        }
    } else {
        int row = gtid >> 1, half = gtid & 1;
        if (row >= B) return;
        unsigned pm = 3u << ((tid & 31) & 30);
        float4* outp = reinterpret_cast<float4*>(g_pooled + row * 64);
        int cnt = mt_c[row];
        const int* idp = mt + row * 50;
        float4 s0={0,0,0,0}, s1={0,0,0,0}, q0={0,0,0,0}, q1={0,0,0,0};
        for (int pos = 0; pos < cnt; pos++) {
            int b = idp[pos] * 4 + half * 2;
            float4 e0 = tag4[b], e1 = tag4[b+1];
            s0.x=fa(s0.x,e0.x); q0.x=fa(q0.x,fm(e0.x,e0.x));
            s0.y=fa(s0.y,e0.y); q0.y=fa(q0.y,fm(e0.y,e0.y));
            s0.z=fa(s0.z,e0.z); q0.z=fa(q0.z,fm(e0.z,e0.z));
            s0.w=fa(s0.w,e0.w); q0.w=fa(q0.w,fm(e0.w,e0.w));
            s1.x=fa(s1.x,e1.x); q1.x=fa(q1.x,fm(e1.x,e1.x));
            s1.y=fa(s1.y,e1.y); q1.y=fa(q1.y,fm(e1.y,e1.y));
            s1.z=fa(s1.z,e1.z); q1.z=fa(q1.z,fm(e1.z,e1.z));
            s1.w=fa(s1.w,e1.w); q1.w=fa(q1.w,fm(e1.w,e1.w));
        }
        float4 v0, v1;
        v0.x=fm(0.5f,__fadd_rn(fm(s0.x,s0.x),-q0.x)); v0.y=fm(0.5f,__fadd_rn(fm(s0.y,s0.y),-q0.y));
        v0.z=fm(0.5f,__fadd_rn(fm(s0.z,s0.z),-q0.z)); v0.w=fm(0.5f,__fadd_rn(fm(s0.w,s0.w),-q0.w));
        v1.x=fm(0.5f,__fadd_rn(fm(s1.x,s1.x),-q1.x)); v1.y=fm(0.5f,__fadd_rn(fm(s1.y,s1.y),-q1.y));
        v1.z=fm(0.5f,__fadd_rn(fm(s1.z,s1.z),-q1.z)); v1.w=fm(0.5f,__fadd_rn(fm(s1.w,s1.w),-q1.w));
        // exchange the 8 partner v's; BOTH threads then evaluate the full
        // 16-term n2 chain in exact d0..d15 order (bitwise same result).
        float p0x=__shfl_xor_sync(pm,v0.x,1), p0y=__shfl_xor_sync(pm,v0.y,1);
        float p0z=__shfl_xor_sync(pm,v0.z,1), p0w=__shfl_xor_sync(pm,v0.w,1);
        float p1x=__shfl_xor_sync(pm,v1.x,1), p1y=__shfl_xor_sync(pm,v1.y,1);
        float p1z=__shfl_xor_sync(pm,v1.z,1), p1w=__shfl_xor_sync(pm,v1.w,1);
        float w0,w1,w2,w3,w4,w5,w6,w7,w8,w9,wa,wb,wc,wd,we,wf;
        if (half == 0) {
            w0=v0.x; w1=v0.y; w2=v0.z; w3=v0.w; w4=v1.x; w5=v1.y; w6=v1.z; w7=v1.w;
            w8=p0x;  w9=p0y;  wa=p0z;  wb=p0w;  wc=p1x;  wd=p1y;  we=p1z;  wf=p1w;
        } else {
            w0=p0x;  w1=p0y;  w2=p0z;  w3=p0w;  w4=p1x;  w5=p1y;  w6=p1z;  w7=p1w;
            w8=v0.x; w9=v0.y; wa=v0.z; wb=v0.w; wc=v1.x; wd=v1.y; we=v1.z; wf=v1.w;
        }
        float n2 = 0.f;
        n2=fa(n2,fm(w0,w0)); n2=fa(n2,fm(w1,w1)); n2=fa(n2,fm(w2,w2)); n2=fa(n2,fm(w3,w3));
        n2=fa(n2,fm(w4,w4)); n2=fa(n2,fm(w5,w5)); n2=fa(n2,fm(w6,w6)); n2=fa(n2,fm(w7,w7));
        n2=fa(n2,fm(w8,w8)); n2=fa(n2,fm(w9,w9)); n2=fa(n2,fm(wa,wa)); n2=fa(n2,fm(wb,wb));
        n2=fa(n2,fm(wc,wc)); n2=fa(n2,fm(wd,wd)); n2=fa(n2,fm(we,we)); n2=fa(n2,fm(wf,wf));
        float n = fmaxf(__fsqrt_rn(n2), 1e-12f);
        float invn = __fdiv_rn(1.f, n);
        v0.x=fm(v0.x,invn); v0.y=fm(v0.y,invn); v0.z=fm(v0.z,invn); v0.w=fm(v0.w,invn);
        v1.x=fm(v1.x,invn); v1.y=fm(v1.y,invn); v1.z=fm(v1.z,invn); v1.w=fm(v1.w,invn);
        outp[12 + half*2] = v0; outp[13 + half*2] = v1;
    }
}

// ---------------------------------------------------------------------------
__global__ void stats_kernel(int B) {
    int d = threadIdx.x;           // 0..63
    float s = 0.f, q = 0.f;
    for (int r = blockIdx.x; r < B; r += 256) {
        float v = g_pooled[r * 64 + d];
        s = fa(s, v);
        q = fa(q, fm(v, v));
    }
    g_part[blockIdx.x * 128 + d] = s;
    g_part[blockIdx.x * 128 + 64 + d] = q;
}

__global__ void bn_kernel(int B) {
    int t = threadIdx.x;
    if (t >= 64) return;
    float s = 0.f, q = 0.f;
    for (int b = 0; b < 256; b++) {
        s = fa(s, g_part[b * 128 + t]);
        q = fa(q, g_part[b * 128 + 64 + t]);
    }
    float invB = 1.f / (float)B;
    float mean = s * invB;
    float var  = q * invB - mean * mean;
    g_mu[t] = mean;
    g_var[t] = var;
}

// ---------------------------------------------------------------------------
// MLP: 2 threads per row. Even lane = inputs 0..55, odd = 56..111.
// Layer-1 partials combined with one shuffle per j; layer-2/3 split by k.
// ---------------------------------------------------------------------------
__global__ __launch_bounds__(128, 4) void mlp2_kernel(
    const int* __restrict__ uid, const int* __restrict__ mid,
    const int* __restrict__ yr,
    const float* __restrict__ emb_user, const float* __restrict__ emb_movie,
    const float* __restrict__ emb_year,
    const float* __restrict__ gamma, const float* __restrict__ beta,
    const float* __restrict__ W1, const float* __restrict__ b1,
    const float* __restrict__ W2, const float* __restrict__ b2,
    const float* __restrict__ W3, const float* __restrict__ b3,
    float* __restrict__ out, int B)
{
    __shared__ float4 sW1t[64 * 28];   // transposed: [j][i/4]
    __shared__ float4 sW2[64 * 8];
    __shared__ float  sb1[64], sMu[64], sR[64], sG[64], sBt[64];
    __shared__ float4 sb2[8], sW3[8];
    __shared__ float  sb3;
    int tid = threadIdx.x;
    for (int idx = tid; idx < 64 * 112; idx += 128) {
        int j = idx / 112, i = idx % 112;
        reinterpret_cast<float*>(sW1t)[j * 112 + i] = W1[i * 64 + j];
    }
    for (int idx = tid; idx < 64 * 8; idx += 128)
        sW2[idx] = reinterpret_cast<const float4*>(W2)[idx];
    if (tid < 64) {
        sb1[tid] = b1[tid];
        sMu[tid] = g_mu[tid];
        sR[tid]  = rsqrtf(__fadd_rn(g_var[tid], 1e-5f));
        sG[tid]  = gamma[tid];
        sBt[tid] = beta[tid];
    }
    if (tid < 8) {
        sb2[tid] = reinterpret_cast<const float4*>(b2)[tid];
        sW3[tid] = reinterpret_cast<const float4*>(W3)[tid];
    }
    if (tid == 0) sb3 = b3[0];
    __syncthreads();

    int gtid = blockIdx.x * 128 + tid;
    int row = gtid >> 1, half = gtid & 1;
    if (row >= B) return;
    unsigned pm = 3u << ((tid & 31) & 30);

    float x[56];
    if (half == 0) {
        const float4* pu = reinterpret_cast<const float4*>(emb_user) + uid[row] * 4;
        const float4* pmv = reinterpret_cast<const float4*>(emb_movie) + mid[row] * 4;
        const float4* py = reinterpret_cast<const float4*>(emb_year) + yr[row] * 4;
        #pragma unroll
        for (int q = 0; q < 4; q++) { float4 v = pu[q];
            x[q*4+0]=v.x; x[q*4+1]=v.y; x[q*4+2]=v.z; x[q*4+3]=v.w; }
        #pragma unroll
        for (int q = 0; q < 4; q++) { float4 v = pmv[q];
            x[16+q*4+0]=v.x; x[16+q*4+1]=v.y; x[16+q*4+2]=v.z; x[16+q*4+3]=v.w; }
        #pragma unroll
        for (int q = 0; q < 4; q++) { float4 v = py[q];
            x[32+q*4+0]=v.x; x[32+q*4+1]=v.y; x[32+q*4+2]=v.z; x[32+q*4+3]=v.w; }
        const float4* pp = reinterpret_cast<const float4*>(g_pooled + row * 64);
        #pragma unroll
        for (int q = 0; q < 2; q++) {          // pooled dims 0..7 -> t = 0..7
            float4 v = pp[q]; int t0 = q * 4;
            x[48+t0+0] = fa(fm(fm(__fadd_rn(v.x, -sMu[t0+0]), sR[t0+0]), sG[t0+0]), sBt[t0+0]);
            x[48+t0+1] = fa(fm(fm(__fadd_rn(v.y, -sMu[t0+1]), sR[t0+1]), sG[t0+1]), sBt[t0+1]);
            x[48+t0+2] = fa(fm(fm(__fadd_rn(v.z, -sMu[t0+2]), sR[t0+2]), sG[t0+2]), sBt[t0+2]);
            x[48+t0+3] = fa(fm(fm(__fadd_rn(v.w, -sMu[t0+3]), sR[t0+3]), sG[t0+3]), sBt[t0+3]);
        }
    } else {
        const float4* pp = reinterpret_cast<const float4*>(g_pooled + row * 64);
        #pragma unroll
        for (int q = 0; q < 14; q++) {         // pooled dims 8..63 -> t = 8..63
            float4 v = pp[2 + q]; int t0 = 8 + q * 4;
            x[q*4+0] = fa(fm(fm(__fadd_rn(v.x, -sMu[t0+0]), sR[t0+0]), sG[t0+0]), sBt[t0+0]);
            x[q*4+1] = fa(fm(fm(__fadd_rn(v.y, -sMu[t0+1]), sR[t0+1]), sG[t0+1]), sBt[t0+1]);
            x[q*4+2] = fa(fm(fm(__fadd_rn(v.z, -sMu[t0+2]), sR[t0+2]), sG[t0+2]), sBt[t0+2]);
            x[q*4+3] = fa(fm(fm(__fadd_rn(v.w, -sMu[t0+3]), sR[t0+3]), sG[t0+3]), sBt[t0+3]);
        }
    }

    float4 acc[4];
    #pragma unroll
    for (int kk = 0; kk < 4; kk++) acc[kk] = sb2[half * 4 + kk];

    #pragma unroll 2
    for (int j = 0; j < 64; j++) {
        float t0 = 0.f, t1 = 0.f, t2 = 0.f, t3 = 0.f;
        const float4* wrow = sW1t + j * 28 + half * 14;
        #pragma unroll
        for (int ii = 0; ii < 14; ii++) {
            float4 w = wrow[ii];
            t0 = fmaf(x[ii*4+0], w.x, t0);
            t1 = fmaf(x[ii*4+1], w.y, t1);
            t2 = fmaf(x[ii*4+2], w.z, t2);
            t3 = fmaf(x[ii*4+3], w.w, t3);
        }
        float s = (t0 + t1) + (t2 + t3);
        float o = __shfl_xor_sync(pm, s, 1);
        float slo = half ? o : s;
        float shi = half ? s : o;
        float t = fmaxf(sb1[j] + (slo + shi), 0.f);
        const float4* w2row = sW2 + j * 8 + half * 4;
        #pragma unroll
        for (int kk = 0; kk < 4; kk++) {
            float4 w = w2row[kk];
            acc[kk].x = fmaf(t, w.x, acc[kk].x);
            acc[kk].y = fmaf(t, w.y, acc[kk].y);
            acc[kk].z = fmaf(t, w.z, acc[kk].z);
            acc[kk].w = fmaf(t, w.w, acc[kk].w);
        }
    }

    float zh = 0.f;
    #pragma unroll
    for (int kk = 0; kk < 4; kk++) {
        float4 w = sW3[half * 4 + kk];
        zh += fmaxf(acc[kk].x, 0.f) * w.x + fmaxf(acc[kk].y, 0.f) * w.y
            + fmaxf(acc[kk].z, 0.f) * w.z + fmaxf(acc[kk].w, 0.f) * w.w;
    }
    float oz = __shfl_xor_sync(pm, zh, 1);
    if (half == 0) {
        float z = sb3 + zh + oz;
        out[row] = 1.f / (1.f + expf(-z));
    }
}

// ---------------------------------------------------------------------------
extern "C" void kernel_launch(void* const* d_in, const int* in_sizes, int n_in,
                              void* d_out, int out_size)
{
    const int* user_id  = (const int*)d_in[0];
    const int* movie_id = (const int*)d_in[1];
    const int* year     = (const int*)d_in[2];
    const int* ug       = (const int*)d_in[3];
    const int* urbv     = (const int*)d_in[4];
    const int* mg       = (const int*)d_in[5];
    const int* mt       = (const int*)d_in[6];
    const int* ug_c     = (const int*)d_in[7];
    const int* urb_c    = (const int*)d_in[8];
    const int* mg_c     = (const int*)d_in[9];
    const int* mt_c     = (const int*)d_in[10];
    const float* emb_user  = (const float*)d_in[11];
    const float* emb_movie = (const float*)d_in[12];
    const float* emb_tag   = (const float*)d_in[13];
    const float* emb_genre = (const float*)d_in[14];
    const float* emb_year  = (const float*)d_in[15];
    const float* at_movie  = (const float*)d_in[16];
    // d_in[17] = at_tagId   (unused by korder)
    // d_in[18] = at_genreId (unused by sum/max)
    const float* gamma = (const float*)d_in[19];
    const float* beta  = (const float*)d_in[20];
    const float* W1 = (const float*)d_in[21];
    const float* b1 = (const float*)d_in[22];
    const float* W2 = (const float*)d_in[23];
    const float* b2 = (const float*)d_in[24];
    const float* W3 = (const float*)d_in[25];
    const float* b3 = (const float*)d_in[26];
    int B = in_sizes[0];

    dim3 pgrid((2 * B + 127) / 128, 4);   // f1/f3 use 2 threads/row
    pool6_kernel<<<pgrid, 128>>>(
        ug, urbv, mg, mt, ug_c, urb_c, mg_c, mt_c,
        emb_movie, emb_tag, emb_genre, at_movie, B);
    stats_kernel<<<256, 64>>>(B);
    bn_kernel<<<1, 64>>>(B);
    mlp2_kernel<<<(2 * B + 127) / 128, 128>>>(
        user_id, movie_id, year, emb_user, emb_movie, emb_year,
        gamma, beta, W1, b1, W2, b2, W3, b3, (float*)d_out, B);
}

// round 10
// speedup vs baseline: 3.3406x; 1.0619x over previous
#include <cuda_runtime.h>
#include <math.h>

#define MAXB 32768

__device__ float  g_pooled[MAXB * 64];   // [B][4 features * 16 dims]
__device__ float  g_part[256 * 128];     // per-block stat partials
__device__ float  g_mu[64];
__device__ float  g_var[64];
__device__ float4 g_W1t4[64 * 28];       // W1 transposed [j][i], filled by bn_kernel

__device__ __forceinline__ float fm(float a, float b) { return __fmul_rn(a, b); }
__device__ __forceinline__ float fa(float a, float b) { return __fadd_rn(a, b); }

// ---------------------------------------------------------------------------
// Pooling: blockIdx.y = feature (warp-uniform). Grid x sized for 4 thr/row.
//   f0 ('sum',   genre): 1 thread/row, genre table in smem.
//   f1 ('atten', movie): 4 threads/row, lane c owns dims 4c..4c+3; M/den
//                        computed redundantly per lane (identical op chain).
//   f2 ('max',   genre): 1 thread/row, per-id L2 precomputed in smem.
//   f3 ('korder', tag):  4 threads/row; n2 rebuilt bit-exactly per lane from
//                        shuffled v-values, full 16-term chain in d-order.
// ---------------------------------------------------------------------------
__global__ __launch_bounds__(128) void pool7_kernel(
    const int* __restrict__ ug, const int* __restrict__ urbv,
    const int* __restrict__ mg, const int* __restrict__ mt,
    const int* __restrict__ ug_c, const int* __restrict__ urb_c,
    const int* __restrict__ mg_c, const int* __restrict__ mt_c,
    const float* __restrict__ emb_movie, const float* __restrict__ emb_tag,
    const float* __restrict__ emb_genre, const float* __restrict__ at_movie,
    int B)
{
    __shared__ float4 s_gen[30 * 4];
    __shared__ float  s_l2[30];
    int tid = threadIdx.x;
    int feat = blockIdx.y;

    if (feat == 0 || feat == 2) {
        if (tid < 120) s_gen[tid] = reinterpret_cast<const float4*>(emb_genre)[tid];
        __syncthreads();
        if (feat == 2) {
            if (tid < 30) {
                float4 e0 = s_gen[tid*4], e1 = s_gen[tid*4+1],
                       e2 = s_gen[tid*4+2], e3 = s_gen[tid*4+3];
                float l2 = 0.f;
                l2=fa(l2,fm(e0.x,e0.x)); l2=fa(l2,fm(e0.y,e0.y)); l2=fa(l2,fm(e0.z,e0.z)); l2=fa(l2,fm(e0.w,e0.w));
                l2=fa(l2,fm(e1.x,e1.x)); l2=fa(l2,fm(e1.y,e1.y)); l2=fa(l2,fm(e1.z,e1.z)); l2=fa(l2,fm(e1.w,e1.w));
                l2=fa(l2,fm(e2.x,e2.x)); l2=fa(l2,fm(e2.y,e2.y)); l2=fa(l2,fm(e2.z,e2.z)); l2=fa(l2,fm(e2.w,e2.w));
                l2=fa(l2,fm(e3.x,e3.x)); l2=fa(l2,fm(e3.y,e3.y)); l2=fa(l2,fm(e3.z,e3.z)); l2=fa(l2,fm(e3.w,e3.w));
                s_l2[tid] = l2;
            }
            __syncthreads();
        }
    }

    int gtid = blockIdx.x * 128 + tid;
    int lane = tid & 31;
    const float4* mov4 = reinterpret_cast<const float4*>(emb_movie);
    const float4* tag4 = reinterpret_cast<const float4*>(emb_tag);

    if (feat == 0) {
        int row = gtid;
        if (row >= B) return;
        float4* outp = reinterpret_cast<float4*>(g_pooled + row * 64);
        int cnt = ug_c[row];
        const int* idp = ug + row * 50;
        float4 p0 = {0,0,0,0}, p1 = {0,0,0,0}, p2 = {0,0,0,0}, p3 = {0,0,0,0};
        for (int pos = 0; pos < cnt; pos++) {
            int id = idp[pos] * 4;
            float4 e0 = s_gen[id], e1 = s_gen[id+1], e2 = s_gen[id+2], e3 = s_gen[id+3];
            p0.x=fa(p0.x,e0.x); p0.y=fa(p0.y,e0.y); p0.z=fa(p0.z,e0.z); p0.w=fa(p0.w,e0.w);
            p1.x=fa(p1.x,e1.x); p1.y=fa(p1.y,e1.y); p1.z=fa(p1.z,e1.z); p1.w=fa(p1.w,e1.w);
            p2.x=fa(p2.x,e2.x); p2.y=fa(p2.y,e2.y); p2.z=fa(p2.z,e2.z); p2.w=fa(p2.w,e2.w);
            p3.x=fa(p3.x,e3.x); p3.y=fa(p3.y,e3.y); p3.z=fa(p3.z,e3.z); p3.w=fa(p3.w,e3.w);
        }
        outp[0]=p0; outp[1]=p1; outp[2]=p2; outp[3]=p3;
    } else if (feat == 1) {
        int row = gtid >> 2, c = gtid & 3;
        if (row >= B) return;
        float4* outp = reinterpret_cast<float4*>(g_pooled + row * 64);
        int cnt = urb_c[row];
        const int* idp = urbv + row * 50;
        float M = (cnt < 50) ? 0.f : -1e30f;
        for (int pos = 0; pos < cnt; pos++)
            M = fmaxf(M, at_movie[idp[pos]]);
        float den = fm((float)(50 - cnt), expf(-M));
        for (int pos = 0; pos < cnt; pos++)
            den = fa(den, expf(__fadd_rn(at_movie[idp[pos]], -M)));
        float invden = __fdiv_rn(1.f, den);
        float4 n0 = {0,0,0,0};
        for (int pos = 0; pos < cnt; pos++) {
            int id = idp[pos];
            float wv = fm(expf(__fadd_rn(at_movie[id], -M)), invden);
            float4 e0 = mov4[id * 4 + c];
            n0.x=fa(n0.x,fm(e0.x,wv)); n0.y=fa(n0.y,fm(e0.y,wv));
            n0.z=fa(n0.z,fm(e0.z,wv)); n0.w=fa(n0.w,fm(e0.w,wv));
        }
        outp[4 + c] = n0;
    } else if (feat == 2) {
        int row = gtid;
        if (row >= B) return;
        float4* outp = reinterpret_cast<float4*>(g_pooled + row * 64);
        int cnt = mg_c[row];
        const int* idp = mg + row * 50;
        int bidx = -1;
        float best = 0.f;
        for (int pos = 0; pos < cnt; pos++) {
            float l2 = s_l2[idp[pos]];
            if (l2 > best) { best = l2; bidx = pos; }
        }
        if (bidx >= 0) {
            int b = idp[bidx] * 4;
            outp[8] = s_gen[b]; outp[9] = s_gen[b+1]; outp[10] = s_gen[b+2]; outp[11] = s_gen[b+3];
        } else {
            float4 z = {0,0,0,0};
            outp[8] = z; outp[9] = z; outp[10] = z; outp[11] = z;
        }
    } else {
        int row = gtid >> 2, c = gtid & 3;
        if (row >= B) return;
        unsigned qm = 0xFu << (lane & 28);
        int qbase = lane & 28;
        float4* outp = reinterpret_cast<float4*>(g_pooled + row * 64);
        int cnt = mt_c[row];
        const int* idp = mt + row * 50;
        float4 s0 = {0,0,0,0}, q0 = {0,0,0,0};
        for (int pos = 0; pos < cnt; pos++) {
            float4 e0 = tag4[idp[pos] * 4 + c];
            s0.x=fa(s0.x,e0.x); q0.x=fa(q0.x,fm(e0.x,e0.x));
            s0.y=fa(s0.y,e0.y); q0.y=fa(q0.y,fm(e0.y,e0.y));
            s0.z=fa(s0.z,e0.z); q0.z=fa(q0.z,fm(e0.z,e0.z));
            s0.w=fa(s0.w,e0.w); q0.w=fa(q0.w,fm(e0.w,e0.w));
        }
        float4 v0;
        v0.x=fm(0.5f,__fadd_rn(fm(s0.x,s0.x),-q0.x)); v0.y=fm(0.5f,__fadd_rn(fm(s0.y,s0.y),-q0.y));
        v0.z=fm(0.5f,__fadd_rn(fm(s0.z,s0.z),-q0.z)); v0.w=fm(0.5f,__fadd_rn(fm(s0.w,s0.w),-q0.w));
        // gather all 16 v's (d-order) from the quad; evaluate full chain.
        float w[16];
        #pragma unroll
        for (int qq = 0; qq < 4; qq++) {
            w[qq*4+0] = __shfl_sync(qm, v0.x, qbase + qq);
            w[qq*4+1] = __shfl_sync(qm, v0.y, qbase + qq);
            w[qq*4+2] = __shfl_sync(qm, v0.z, qbase + qq);
            w[qq*4+3] = __shfl_sync(qm, v0.w, qbase + qq);
        }
        float n2 = 0.f;
        #pragma unroll
        for (int d = 0; d < 16; d++) n2 = fa(n2, fm(w[d], w[d]));
        float n = fmaxf(__fsqrt_rn(n2), 1e-12f);
        float invn = __fdiv_rn(1.f, n);
        v0.x=fm(v0.x,invn); v0.y=fm(v0.y,invn); v0.z=fm(v0.z,invn); v0.w=fm(v0.w,invn);
        outp[12 + c] = v0;
    }
}

// ---------------------------------------------------------------------------
__global__ void stats_kernel(int B) {
    int d = threadIdx.x;           // 0..63
    float s = 0.f, q = 0.f;
    for (int r = blockIdx.x; r < B; r += 256) {
        float v = g_pooled[r * 64 + d];
        s = fa(s, v);
        q = fa(q, fm(v, v));
    }
    g_part[blockIdx.x * 128 + d] = s;
    g_part[blockIdx.x * 128 + 64 + d] = q;
}

// Finalize BN stats AND pre-transpose W1 (so mlp blocks stage coalesced).
__global__ void bn_kernel(const float* __restrict__ W1, int B) {
    int t = threadIdx.x;
    if (t < 64) {
        float s = 0.f, q = 0.f;
        for (int b = 0; b < 256; b++) {
            s = fa(s, g_part[b * 128 + t]);
            q = fa(q, g_part[b * 128 + 64 + t]);
        }
        float invB = 1.f / (float)B;
        float mean = s * invB;
        float var  = q * invB - mean * mean;
        g_mu[t] = mean;
        g_var[t] = var;
    }
    float* w1t = reinterpret_cast<float*>(g_W1t4);
    for (int idx = t; idx < 64 * 112; idx += 128) {
        int j = idx / 112, i = idx % 112;
        w1t[j * 112 + i] = W1[i * 64 + j];
    }
}

// ---------------------------------------------------------------------------
// MLP: 2 threads per row (even = inputs 0..55, odd = 56..111); weights staged
// from the PRE-TRANSPOSED g_W1t4 with coalesced float4 loads.
// ---------------------------------------------------------------------------
__global__ __launch_bounds__(128, 4) void mlp3_kernel(
    const int* __restrict__ uid, const int* __restrict__ mid,
    const int* __restrict__ yr,
    const float* __restrict__ emb_user, const float* __restrict__ emb_movie,
    const float* __restrict__ emb_year,
    const float* __restrict__ gamma, const float* __restrict__ beta,
    const float* __restrict__ b1,
    const float* __restrict__ W2, const float* __restrict__ b2,
    const float* __restrict__ W3, const float* __restrict__ b3,
    float* __restrict__ out, int B)
{
    __shared__ float4 sW1t[64 * 28];   // [j][i/4]
    __shared__ float4 sW2[64 * 8];
    __shared__ float  sb1[64], sMu[64], sR[64], sG[64], sBt[64];
    __shared__ float4 sb2[8], sW3[8];
    __shared__ float  sb3;
    int tid = threadIdx.x;
    #pragma unroll
    for (int k = 0; k < 14; k++)
        sW1t[tid + 128 * k] = g_W1t4[tid + 128 * k];
    for (int idx = tid; idx < 64 * 8; idx += 128)
        sW2[idx] = reinterpret_cast<const float4*>(W2)[idx];
    if (tid < 64) {
        sb1[tid] = b1[tid];
        sMu[tid] = g_mu[tid];
        sR[tid]  = rsqrtf(__fadd_rn(g_var[tid], 1e-5f));
        sG[tid]  = gamma[tid];
        sBt[tid] = beta[tid];
    }
    if (tid < 8) {
        sb2[tid] = reinterpret_cast<const float4*>(b2)[tid];
        sW3[tid] = reinterpret_cast<const float4*>(W3)[tid];
    }
    if (tid == 0) sb3 = b3[0];
    __syncthreads();

    int gtid = blockIdx.x * 128 + tid;
    int row = gtid >> 1, half = gtid & 1;
    if (row >= B) return;
    unsigned pm = 3u << ((tid & 31) & 30);

    float x[56];
    if (half == 0) {
        const float4* pu = reinterpret_cast<const float4*>(emb_user) + uid[row] * 4;
        const float4* pmv = reinterpret_cast<const float4*>(emb_movie) + mid[row] * 4;
        const float4* py = reinterpret_cast<const float4*>(emb_year) + yr[row] * 4;
        #pragma unroll
        for (int q = 0; q < 4; q++) { float4 v = pu[q];
            x[q*4+0]=v.x; x[q*4+1]=v.y; x[q*4+2]=v.z; x[q*4+3]=v.w; }
        #pragma unroll
        for (int q = 0; q < 4; q++) { float4 v = pmv[q];
            x[16+q*4+0]=v.x; x[16+q*4+1]=v.y; x[16+q*4+2]=v.z; x[16+q*4+3]=v.w; }
        #pragma unroll
        for (int q = 0; q < 4; q++) { float4 v = py[q];
            x[32+q*4+0]=v.x; x[32+q*4+1]=v.y; x[32+q*4+2]=v.z; x[32+q*4+3]=v.w; }
        const float4* pp = reinterpret_cast<const float4*>(g_pooled + row * 64);
        #pragma unroll
        for (int q = 0; q < 2; q++) {          // pooled dims 0..7 -> t = 0..7
            float4 v = pp[q]; int t0 = q * 4;
            x[48+t0+0] = fa(fm(fm(__fadd_rn(v.x, -sMu[t0+0]), sR[t0+0]), sG[t0+0]), sBt[t0+0]);
            x[48+t0+1] = fa(fm(fm(__fadd_rn(v.y, -sMu[t0+1]), sR[t0+1]), sG[t0+1]), sBt[t0+1]);
            x[48+t0+2] = fa(fm(fm(__fadd_rn(v.z, -sMu[t0+2]), sR[t0+2]), sG[t0+2]), sBt[t0+2]);
            x[48+t0+3] = fa(fm(fm(__fadd_rn(v.w, -sMu[t0+3]), sR[t0+3]), sG[t0+3]), sBt[t0+3]);
        }
    } else {
        const float4* pp = reinterpret_cast<const float4*>(g_pooled + row * 64);
        #pragma unroll
        for (int q = 0; q < 14; q++) {         // pooled dims 8..63 -> t = 8..63
            float4 v = pp[2 + q]; int t0 = 8 + q * 4;
            x[q*4+0] = fa(fm(fm(__fadd_rn(v.x, -sMu[t0+0]), sR[t0+0]), sG[t0+0]), sBt[t0+0]);
            x[q*4+1] = fa(fm(fm(__fadd_rn(v.y, -sMu[t0+1]), sR[t0+1]), sG[t0+1]), sBt[t0+1]);
            x[q*4+2] = fa(fm(fm(__fadd_rn(v.z, -sMu[t0+2]), sR[t0+2]), sG[t0+2]), sBt[t0+2]);
            x[q*4+3] = fa(fm(fm(__fadd_rn(v.w, -sMu[t0+3]), sR[t0+3]), sG[t0+3]), sBt[t0+3]);
        }
    }

    float4 acc[4];
    #pragma unroll
    for (int kk = 0; kk < 4; kk++) acc[kk] = sb2[half * 4 + kk];

    #pragma unroll 2
    for (int j = 0; j < 64; j++) {
        float t0 = 0.f, t1 = 0.f, t2 = 0.f, t3 = 0.f;
        const float4* wrow = sW1t + j * 28 + half * 14;
        #pragma unroll
        for (int ii = 0; ii < 14; ii++) {
            float4 w = wrow[ii];
            t0 = fmaf(x[ii*4+0], w.x, t0);
            t1 = fmaf(x[ii*4+1], w.y, t1);
            t2 = fmaf(x[ii*4+2], w.z, t2);
            t3 = fmaf(x[ii*4+3], w.w, t3);
        }
        float s = (t0 + t1) + (t2 + t3);
        float o = __shfl_xor_sync(pm, s, 1);
        float slo = half ? o : s;
        float shi = half ? s : o;
        float t = fmaxf(sb1[j] + (slo + shi), 0.f);
        const float4* w2row = sW2 + j * 8 + half * 4;
        #pragma unroll
        for (int kk = 0; kk < 4; kk++) {
            float4 w = w2row[kk];
            acc[kk].x = fmaf(t, w.x, acc[kk].x);
            acc[kk].y = fmaf(t, w.y, acc[kk].y);
            acc[kk].z = fmaf(t, w.z, acc[kk].z);
            acc[kk].w = fmaf(t, w.w, acc[kk].w);
        }
    }

    float zh = 0.f;
    #pragma unroll
    for (int kk = 0; kk < 4; kk++) {
        float4 w = sW3[half * 4 + kk];
        zh += fmaxf(acc[kk].x, 0.f) * w.x + fmaxf(acc[kk].y, 0.f) * w.y
            + fmaxf(acc[kk].z, 0.f) * w.z + fmaxf(acc[kk].w, 0.f) * w.w;
    }
    float oz = __shfl_xor_sync(pm, zh, 1);
    if (half == 0) {
        float z = sb3 + zh + oz;
        out[row] = 1.f / (1.f + expf(-z));
    }
}

// ---------------------------------------------------------------------------
extern "C" void kernel_launch(void* const* d_in, const int* in_sizes, int n_in,
                              void* d_out, int out_size)
{
    const int* user_id  = (const int*)d_in[0];
    const int* movie_id = (const int*)d_in[1];
    const int* year     = (const int*)d_in[2];
    const int* ug       = (const int*)d_in[3];
    const int* urbv     = (const int*)d_in[4];
    const int* mg       = (const int*)d_in[5];
    const int* mt       = (const int*)d_in[6];
    const int* ug_c     = (const int*)d_in[7];
    const int* urb_c    = (const int*)d_in[8];
    const int* mg_c     = (const int*)d_in[9];
    const int* mt_c     = (const int*)d_in[10];
    const float* emb_user  = (const float*)d_in[11];
    const float* emb_movie = (const float*)d_in[12];
    const float* emb_tag   = (const float*)d_in[13];
    const float* emb_genre = (const float*)d_in[14];
    const float* emb_year  = (const float*)d_in[15];
    const float* at_movie  = (const float*)d_in[16];
    // d_in[17] = at_tagId   (unused by korder)
    // d_in[18] = at_genreId (unused by sum/max)
    const float* gamma = (const float*)d_in[19];
    const float* beta  = (const float*)d_in[20];
    const float* W1 = (const float*)d_in[21];
    const float* b1 = (const float*)d_in[22];
    const float* W2 = (const float*)d_in[23];
    const float* b2 = (const float*)d_in[24];
    const float* W3 = (const float*)d_in[25];
    const float* b3 = (const float*)d_in[26];
    int B = in_sizes[0];

    dim3 pgrid((4 * B + 127) / 128, 4);   // f1/f3 use 4 threads/row
    pool7_kernel<<<pgrid, 128>>>(
        ug, urbv, mg, mt, ug_c, urb_c, mg_c, mt_c,
        emb_movie, emb_tag, emb_genre, at_movie, B);
    stats_kernel<<<256, 64>>>(B);
    bn_kernel<<<1, 128>>>(W1, B);
    mlp3_kernel<<<(2 * B + 127) / 128, 128>>>(
        user_id, movie_id, year, emb_user, emb_movie, emb_year,
        gamma, beta, b1, W2, b2, W3, b3, (float*)d_out, B);
}